// round 5
// baseline (speedup 1.0000x reference)
#include <cuda_runtime.h>
#include <cstddef>

// ---------------------------------------------------------------------------
// Problem constants
// ---------------------------------------------------------------------------
constexpr int B_  = 2;
constexpr int C_  = 64;
constexpr int C4_ = 256;
constexpr int H_  = 64;
constexpr int W_  = 96;
constexpr int HW_ = H_ * W_;
constexpr int NSB = 2 * B_;   // side * batch slots

typedef unsigned long long ull;

// Scratch (device globals: no allocations allowed). Layout [side*B+b][C4][HW]
__device__ float g_t1[(size_t)NSB * C4_ * HW_];
__device__ float g_t2[(size_t)NSB * C4_ * HW_];
__device__ float g_Q [(size_t)B_ * C_  * HW_];
__device__ float g_K [(size_t)B_ * C_  * HW_];

// ---------------------------------------------------------------------------
// f32x2 helpers (sm_100+ packed fp32 — exact, two independent IEEE FMAs)
// ---------------------------------------------------------------------------
__device__ __forceinline__ ull pk2(float a, float b) {
    ull r;
    asm("mov.b64 %0, {%1, %2};" : "=l"(r)
        : "r"(__float_as_uint(a)), "r"(__float_as_uint(b)));
    return r;
}
__device__ __forceinline__ void fma2(ull& d, ull a, ull b) {
    asm("fma.rn.f32x2 %0, %1, %2, %0;" : "+l"(d) : "l"(a), "l"(b));
}
__device__ __forceinline__ void unpk2(ull v, float& lo, float& hi) {
    unsigned l, h;
    asm("mov.b64 {%0, %1}, %2;" : "=r"(l), "=r"(h) : "l"(v));
    lo = __uint_as_float(l); hi = __uint_as_float(h);
}

// ---------------------------------------------------------------------------
// Grouped 3x3 conv (groups=4, in=out=256ch), stride 1, pad 1. Both sides in
// one launch: z = s*8 + b*4 + g.
// MODE 1: input = BN(cat[side]) on load; output = leaky(conv + bias)
// MODE 2: input = t1[side]; output = conv + bias + BN(cat[side]) residual
// Tile 8 rows x 16 cols x 64 oc per block; 256 threads; thread = 8oc x 4px
// (32 accumulator registers -> no spills under the 128-reg cap).
// ---------------------------------------------------------------------------
constexpr int TH   = 8;
constexpr int TW   = 16;
constexpr int ICB  = 8;
constexpr int INROW   = TW + 2;   // 18 valid cols
constexpr int INPITCH = 20;       // even pitch -> float2-aligned rows

constexpr int CONV_W2   = ICB * 9 * 64;            // ull count  (36864 B)
constexpr int CONV_IN   = ICB * 10 * INPITCH;      // float count (6400 B)
constexpr int CONV_SMEM = CONV_W2 * 8 + CONV_IN * 4 + 2 * 64 * 4;

template <int MODE>
__global__ __launch_bounds__(256, 2)
void conv3x3_kernel(const float* __restrict__ catL,
                    const float* __restrict__ catR,
                    const float* __restrict__ tin,
                    const float* __restrict__ wgt,   // (256, 64, 3, 3)
                    const float* __restrict__ bias,  // (256)
                    const float* __restrict__ bn_g,
                    const float* __restrict__ bn_b,
                    const float* __restrict__ bn_m,
                    const float* __restrict__ bn_v,
                    float* __restrict__ out)
{
    extern __shared__ unsigned char csm[];
    ull*   s_w2 = (ull*)csm;                       // [oc*72 + c*9 + tap]
    float* s_in = (float*)(s_w2 + CONV_W2);        // [c][10][20]
    float* s_sc = s_in + CONV_IN;
    float* s_sh = s_sc + 64;

    const int tid = threadIdx.x;
    const int bz  = blockIdx.z;        // s*8 + b*4 + g
    const int s   = bz >> 3;
    const int b   = (bz >> 2) & 1;
    const int g   = bz & 3;
    const int sb  = s * B_ + b;
    const int y0  = blockIdx.y * TH;
    const int x0  = blockIdx.x * TW;
    const int chbase = g * 64;

    const float* cat = s ? catR : catL;

    if (tid < 64) {
        const int ch = chbase + tid;
        const float sc = bn_g[ch] * rsqrtf(bn_v[ch] + 1e-5f);
        s_sc[tid] = sc;
        s_sh[tid] = bn_b[ch] - bn_m[ch] * sc;
    }

    const int og   = tid >> 5;        // 0..7 (out-channel octet)
    const int p    = tid & 31;
    const int rowp = p >> 2;          // 0..7
    const int colp = (p & 3) * 4;     // 0,4,8,12

    ull acc2[8][2];
#pragma unroll
    for (int o = 0; o < 8; o++) { acc2[o][0] = 0ULL; acc2[o][1] = 0ULL; }

    const float* inb = (MODE == 1)
        ? cat + (size_t)(b * C4_ + chbase) * HW_
        : tin + (size_t)(sb * C4_ + chbase) * HW_;

    __syncthreads();  // s_sc/s_sh ready

    for (int icb = 0; icb < 64; icb += ICB) {
        // stage input tile (BN on load for MODE 1)
        for (int idx = tid; idx < ICB * 10 * INROW; idx += 256) {
            const int c   = idx / (10 * INROW);
            const int rem = idx % (10 * INROW);
            const int r   = rem / INROW;
            const int cc  = rem % INROW;
            const int gy  = y0 - 1 + r;
            const int gx  = x0 - 1 + cc;
            float v = 0.f;
            if ((unsigned)gy < (unsigned)H_ && (unsigned)gx < (unsigned)W_) {
                v = inb[(size_t)(icb + c) * HW_ + gy * W_ + gx];
                if (MODE == 1) v = v * s_sc[icb + c] + s_sh[icb + c];
            }
            s_in[(c * 10 + r) * INPITCH + cc] = v;
        }
        // stage weights duplicated into f32x2: s_w2[oc*72 + c*9 + tap]
        for (int idx = tid; idx < ICB * 576; idx += 256) {
            const int oc  = idx / 72;
            const int r   = idx % 72;    // c*9 + tap
            const int c   = r / 9;
            const int tap = r % 9;
            const float w = wgt[(size_t)(chbase + oc) * 576 + (icb + c) * 9 + tap];
            s_w2[oc * 72 + r] = pk2(w, w);
        }
        __syncthreads();

#pragma unroll 2
        for (int c = 0; c < ICB; c++) {
            // per row: cols colp..colp+5 as 3 aligned float2 + 2 odd pairs
            ull xp[3][3][2];
#pragma unroll
            for (int kh = 0; kh < 3; kh++) {
                const float2* rp = (const float2*)&s_in[(c * 10 + rowp + kh) * INPITCH + colp];
                const float2 e0 = rp[0], e1 = rp[1], e2 = rp[2];
                const ull E0 = pk2(e0.x, e0.y);
                const ull E1 = pk2(e1.x, e1.y);
                const ull E2 = pk2(e2.x, e2.y);
                const ull O0 = pk2(e0.y, e1.x);
                const ull O1 = pk2(e1.y, e2.x);
                xp[kh][0][0] = E0; xp[kh][0][1] = E1;   // tap t=0: x0..x3
                xp[kh][1][0] = O0; xp[kh][1][1] = O1;   // tap t=1: x1..x4
                xp[kh][2][0] = E1; xp[kh][2][1] = E2;   // tap t=2: x2..x5
            }
            const ull* wbase = &s_w2[(og * 8) * 72 + c * 9];
#pragma unroll
            for (int kh = 0; kh < 3; kh++) {
#pragma unroll
                for (int t = 0; t < 3; t++) {
                    const int tap = kh * 3 + t;
                    const ull xa = xp[kh][t][0];
                    const ull xb = xp[kh][t][1];
#pragma unroll
                    for (int o = 0; o < 8; o++) {
                        const ull w = wbase[o * 72 + tap];   // uniform broadcast
                        fma2(acc2[o][0], w, xa);
                        fma2(acc2[o][1], w, xb);
                    }
                }
            }
        }
        __syncthreads();
    }

    // epilogue
    const float* catb = cat + (size_t)(b * C4_ + chbase) * HW_;
    float*       outb = out + (size_t)(sb * C4_ + chbase) * HW_;
    const int y = y0 + rowp;
#pragma unroll
    for (int o = 0; o < 8; o++) {
        const int oc = og * 8 + o;
        const float bv = bias[chbase + oc];
#pragma unroll
        for (int pq = 0; pq < 2; pq++) {
            float v0, v1;
            unpk2(acc2[o][pq], v0, v1);
#pragma unroll
            for (int half = 0; half < 2; half++) {
                const int x = x0 + colp + 2 * pq + half;
                float v = (half ? v1 : v0) + bv;
                if (MODE == 1) {
                    v = (v > 0.f) ? v : 0.1f * v;         // LeakyReLU(0.1)
                } else {
                    const float cv = catb[(size_t)oc * HW_ + y * W_ + x];
                    v += cv * s_sc[oc] + s_sh[oc];
                }
                outb[(size_t)oc * HW_ + y * W_ + x] = v;
            }
        }
    }
}

// ---------------------------------------------------------------------------
// Grouped 1x1 conv: 64oc <- 256ic, groups=4 (16oc per group reads 64ic).
// z = s*8 + b*4 + g. Each thread: 4 consecutive pixels, all 16 oc.
// ---------------------------------------------------------------------------
__global__ __launch_bounds__(256)
void conv1x1_kernel(const float* __restrict__ in,    // t2 [sb][256][HW]
                    const float* __restrict__ bqw, const float* __restrict__ bqb,
                    const float* __restrict__ bsw, const float* __restrict__ bsb,
                    float* __restrict__ Qb, float* __restrict__ Kb)
{
    __shared__ ull s_wt[16 * 64];   // duplicated weights, 8KB

    const int tid = threadIdx.x;
    const int bz  = blockIdx.z;
    const int s   = bz >> 3;
    const int b   = (bz >> 2) & 1;
    const int g   = bz & 3;

    const float* wsel = s ? bsw : bqw;
    const float* bsel = s ? bsb : bqb;

    for (int idx = tid; idx < 1024; idx += 256) {
        const int o  = idx >> 6;
        const int ic = idx & 63;
        const float w = wsel[(g * 16 + o) * 64 + ic];
        s_wt[idx] = pk2(w, w);
    }
    __syncthreads();

    const int px0 = blockIdx.x * 1024 + tid * 4;
    const float* ip = in + (size_t)((s * B_ + b) * C4_ + g * 64) * HW_ + px0;

    ull acc[16][2];
#pragma unroll
    for (int o = 0; o < 16; o++) {
        const float bv = bsel[g * 16 + o];
        acc[o][0] = pk2(bv, bv);
        acc[o][1] = pk2(bv, bv);
    }

    for (int ic = 0; ic < 64; ic++) {
        const float4 v = *(const float4*)&ip[(size_t)ic * HW_];
        const ull v01 = pk2(v.x, v.y);
        const ull v23 = pk2(v.z, v.w);
        const ull* wp = &s_wt[ic];
#pragma unroll
        for (int o = 0; o < 16; o++) {
            const ull w = wp[o * 64];   // broadcast
            fma2(acc[o][0], w, v01);
            fma2(acc[o][1], w, v23);
        }
    }

    float* op = (s ? Kb : Qb) + (size_t)(b * C_ + g * 16) * HW_ + px0;
#pragma unroll
    for (int o = 0; o < 16; o++) {
        float4 r;
        unpk2(acc[o][0], r.x, r.y);
        unpk2(acc[o][1], r.z, r.w);
        *(float4*)&op[(size_t)o * HW_] = r;
    }
}

// ---------------------------------------------------------------------------
// Attention kernel. Grid (H, B, dir). 256 threads, 3 blocks/SM.
// dir 0 = r2l (K-window/Q-center -> outL from xR)
// dir 1 = l2r (Q-window/K-center -> outR from xL, value coords still r2l).
// Window strips stored channel-PAIRED as float2 (one LDS.64 feeds 2 channels).
// 4-col zero padding -> no bounds predicates. Mean subtraction dropped
// (softmax-invariant).
// ---------------------------------------------------------------------------
constexpr int ROWP2  = 105;             // row pitch in float2 units
constexpr int CSTR2  = 8 * ROWP2 + 5;   // 845, channel-pair stride (float2)
constexpr int NPAIR  = 4;               // channel pairs per chunk (8 channels)
constexpr int WIN_F2 = NPAIR * CSTR2;   // 3380 float2
constexpr int CEN_F2 = NPAIR * 96;      // 384 float2
constexpr int MPITCH = 66;
constexpr int M_F    = 96 * MPITCH;     // 6336 floats
constexpr int OUT_F  = 8 * 96;          // 768 floats
constexpr int ATT_SMEM = WIN_F2 * 8 + CEN_F2 * 8 + M_F * 4 + OUT_F * 4 + 5 * 96 * 4;

__global__ __launch_bounds__(256, 3)
void attention_kernel(const float* __restrict__ Qf, const float* __restrict__ Kf,
                      const float* __restrict__ xL, const float* __restrict__ xR,
                      const int* __restrict__ dL, const int* __restrict__ dR,
                      float* __restrict__ outL, float* __restrict__ outR)
{
    extern __shared__ float smem[];
    float2* s_win2 = (float2*)smem;                 // WIN_F2
    float2* s_cen2 = s_win2 + WIN_F2;               // CEN_F2
    float*  s_M    = (float*)(s_cen2 + CEN_F2);     // M_F
    float*  s_out  = s_M + M_F;                     // OUT_F
    int*    s_cc   = (int*)(s_out + OUT_F);         // 96  logits centers
    int*    s_cv   = s_cc + 96;                     // 96  value centers (= cr)
    int*    s_sval = s_cv + 96;                     // 96  softmax validity
    int*    s_vval = s_sval + 96;                   // 96  value validity (= vR)
    float*  s_mask = (float*)(s_vval + 96);         // 96  output mask

    const int i   = blockIdx.x;
    const int b   = blockIdx.y;
    const int z   = blockIdx.z;                     // 0=r2l, 1=l2r
    const int tid = threadIdx.x;

    if (tid < 96) {
        const int j  = tid;
        const int dl = dL[(b * H_ + i) * W_ + j];
        const int dr = dR[(b * H_ + i) * W_ + j];
        const int cr = max(j - dl, 0);
        const int cl = min(j + dr, W_ - 1);
        const int rowok = (i + 4) < H_;
        const int vR = (rowok && cr < W_ - 4) ? 1 : 0;
        const int vL = (rowok && cl < W_ - 4) ? 1 : 0;
        s_cc[j]   = z ? cl : cr;
        s_cv[j]   = cr;                             // value coords always r2l
        s_sval[j] = z ? vL : vR;
        s_vval[j] = vR;                             // value validity always vR
        s_mask[j] = z ? ((j + dr <= W_ - 1) ? 1.f : 0.f)
                      : ((j - dl >= 0)      ? 1.f : 0.f);
    }
    for (int idx = tid; idx < WIN_F2; idx += 256)
        s_win2[idx] = make_float2(0.f, 0.f);        // incl. pad columns
    for (int idx = tid; idx < M_F; idx += 256) s_M[idx] = 0.f;
    __syncthreads();

    const float* winsrc = z ? Qf : Kf;
    const float* censrc = z ? Kf : Qf;
    const int kbit  = tid & 1;
    const int koff  = kbit * 32;
    const int aoff2 = kbit * 4 * ROWP2;
    const int jlog  = tid >> 1;

    // ---- logits: 8 chunks of 4 channel pairs ----
    for (int cb = 0; cb < 8; cb++) {
        const int c0 = cb * 8;
        const float* wsb = winsrc + (size_t)(b * C_ + c0) * HW_;
        for (int idx = tid; idx < NPAIR * 768; idx += 256) {
            const int cp  = idx / 768;
            const int rem = idx - cp * 768;          // a*96 + col
            const int a   = rem / 96;
            const int col = rem - a * 96;
            const int gy  = i - 4 + a;
            float v0 = 0.f, v1 = 0.f;
            if ((unsigned)gy < (unsigned)H_) {
                const size_t o = (size_t)(2 * cp) * HW_ + gy * W_ + col;
                v0 = wsb[o];
                v1 = wsb[o + HW_];
            }
            s_win2[cp * CSTR2 + a * ROWP2 + 4 + col] = make_float2(v0, v1);
        }
        const float* csb = censrc + (size_t)(b * C_ + c0) * HW_ + (size_t)i * W_;
        for (int idx = tid; idx < NPAIR * 96; idx += 256) {
            const int cp = idx / 96, j = idx - cp * 96;
            const size_t o = (size_t)(2 * cp) * HW_ + j;
            s_cen2[idx] = make_float2(csb[o], csb[o + HW_]);
        }
        __syncthreads();

        if (tid < 192) {
            const int cc = s_cc[jlog];
            float acc[32];
#pragma unroll
            for (int kk = 0; kk < 32; kk++) acc[kk] = 0.f;
#pragma unroll
            for (int cp = 0; cp < NPAIR; cp++) {
                const float2 cen = s_cen2[cp * 96 + jlog];
                const float2* wb = s_win2 + cp * CSTR2 + cc + aoff2;
#pragma unroll
                for (int kk = 0; kk < 32; kk++) {
                    const float2 w = wb[(kk >> 3) * ROWP2 + (kk & 7)];
                    acc[kk] = fmaf(cen.x, w.x, fmaf(cen.y, w.y, acc[kk]));
                }
            }
            float* Mrow = s_M + jlog * MPITCH + koff;
#pragma unroll
            for (int kk = 0; kk < 32; kk++) Mrow[kk] += acc[kk];
        }
        __syncthreads();
    }

    // ---- softmax ----
    if (tid < 96) {
        float* row = s_M + tid * MPITCH;
        if (!s_sval[tid]) {
#pragma unroll
            for (int k = 0; k < 64; k++) row[k] = 1.f / 64.f;
        } else {
            float mx = row[0];
#pragma unroll
            for (int k = 1; k < 64; k++) mx = fmaxf(mx, row[k]);
            float ssum = 0.f;
#pragma unroll
            for (int k = 0; k < 64; k++) {
                const float e = __expf(row[k] - mx);
                row[k] = e; ssum += e;
            }
            const float inv = 1.f / ssum;
#pragma unroll
            for (int k = 0; k < 64; k++) row[k] *= inv;
        }
    }
    __syncthreads();

    // ---- value pass: 8 chunks of 4 channel pairs ----
    const float* valsrc  = z ? xL : xR;
    const float* basesrc = z ? xR : xL;
    float*       outdst  = z ? outR : outL;
    const int cpair = tid & 3;
    const int jg    = tid >> 2;          // 0..63

    for (int cb = 0; cb < 8; cb++) {
        const int c0 = cb * 8;
        const float* vsb = valsrc + (size_t)(b * C_ + c0) * HW_;
        for (int idx = tid; idx < NPAIR * 768; idx += 256) {
            const int cp  = idx / 768;
            const int rem = idx - cp * 768;
            const int a   = rem / 96;
            const int col = rem - a * 96;
            const int gy  = i - 4 + a;
            float v0 = 0.f, v1 = 0.f;
            if ((unsigned)gy < (unsigned)H_) {
                const size_t o = (size_t)(2 * cp) * HW_ + gy * W_ + col;
                v0 = vsb[o];
                v1 = vsb[o + HW_];
            }
            s_win2[cp * CSTR2 + a * ROWP2 + 4 + col] = make_float2(v0, v1);
        }
        __syncthreads();

        const float2* wbase = s_win2 + cpair * CSTR2;
#pragma unroll
        for (int m = 0; m < 2; m++) {
            const int j = jg + 64 * m;
            if (j < 96) {
                float aL = 0.f, aH = 0.f;
                if (s_vval[j]) {
                    const float2* wb   = wbase + s_cv[j];
                    const float*  Mrow = s_M + j * MPITCH;
#pragma unroll
                    for (int kp = 0; kp < 32; kp++) {
                        const float2 mv = *(const float2*)(Mrow + 2 * kp);
                        const int k0 = 2 * kp, k1 = 2 * kp + 1;
                        const float2 w0 = wb[(k0 >> 3) * ROWP2 + (k0 & 7)];
                        const float2 w1 = wb[(k1 >> 3) * ROWP2 + (k1 & 7)];
                        aL = fmaf(mv.x, w0.x, fmaf(mv.y, w1.x, aL));
                        aH = fmaf(mv.x, w0.y, fmaf(mv.y, w1.y, aH));
                    }
                }
                s_out[(2 * cpair) * 96 + j]     = aL * s_mask[j];
                s_out[(2 * cpair + 1) * 96 + j] = aH * s_mask[j];
            }
        }
        __syncthreads();

        for (int t = 0; t < 3; t++) {
            const int idx = tid + t * 256;
            const int c = idx / 96, j = idx - c * 96;
            const size_t gidx = ((size_t)(b * C_ + c0 + c) * H_ + i) * W_ + j;
            outdst[gidx] = basesrc[gidx] + s_out[idx];
        }
        __syncthreads();
    }
}

// ---------------------------------------------------------------------------
// Host launcher
// ---------------------------------------------------------------------------
extern "C" void kernel_launch(void* const* d_in, const int* in_sizes, int n_in,
                              void* d_out, int out_size)
{
    const float *xL, *xR, *catL, *catR;
    const float *bng, *bnb, *bnm, *bnv, *w1, *b1, *w2, *b2, *bqw, *bqb, *bsw, *bsb;
    const int *dL, *dR;

    const bool dict_order = (n_in >= 18) && (in_sizes[4] == B_ * H_ * W_);
    if (dict_order) {
        xL   = (const float*)d_in[0];  xR   = (const float*)d_in[1];
        catL = (const float*)d_in[2];  catR = (const float*)d_in[3];
        dL   = (const int*)  d_in[4];  dR   = (const int*)  d_in[5];
        bng  = (const float*)d_in[6];  bnb  = (const float*)d_in[7];
        bnm  = (const float*)d_in[8];  bnv  = (const float*)d_in[9];
        w1   = (const float*)d_in[10]; b1   = (const float*)d_in[11];
        w2   = (const float*)d_in[12]; b2   = (const float*)d_in[13];
        bqw  = (const float*)d_in[14]; bqb  = (const float*)d_in[15];
        bsw  = (const float*)d_in[16]; bsb  = (const float*)d_in[17];
    } else {
        xL   = (const float*)d_in[0];  xR   = (const float*)d_in[1];
        catL = (const float*)d_in[2];  catR = (const float*)d_in[3];
        bng  = (const float*)d_in[4];  bnb  = (const float*)d_in[5];
        bnm  = (const float*)d_in[6];  bnv  = (const float*)d_in[7];
        w1   = (const float*)d_in[8];  b1   = (const float*)d_in[9];
        w2   = (const float*)d_in[10]; b2   = (const float*)d_in[11];
        bqw  = (const float*)d_in[12]; bqb  = (const float*)d_in[13];
        bsw  = (const float*)d_in[14]; bsb  = (const float*)d_in[15];
        dL   = (const int*)  d_in[16]; dR   = (const int*)  d_in[17];
    }

    float *t1, *t2, *Qb, *Kb;
    cudaGetSymbolAddress((void**)&t1, g_t1);
    cudaGetSymbolAddress((void**)&t2, g_t2);
    cudaGetSymbolAddress((void**)&Qb, g_Q);
    cudaGetSymbolAddress((void**)&Kb, g_K);

    cudaFuncSetAttribute(conv3x3_kernel<1>,
                         cudaFuncAttributeMaxDynamicSharedMemorySize, CONV_SMEM);
    cudaFuncSetAttribute(conv3x3_kernel<2>,
                         cudaFuncAttributeMaxDynamicSharedMemorySize, CONV_SMEM);
    cudaFuncSetAttribute(attention_kernel,
                         cudaFuncAttributeMaxDynamicSharedMemorySize, ATT_SMEM);

    const dim3 cgrid(W_ / TW, H_ / TH, NSB * 4);   // (6, 8, 16) = 768 blocks

    conv3x3_kernel<1><<<cgrid, 256, CONV_SMEM>>>(catL, catR, nullptr, w1, b1,
                                                 bng, bnb, bnm, bnv, t1);
    conv3x3_kernel<2><<<cgrid, 256, CONV_SMEM>>>(catL, catR, t1, w2, b2,
                                                 bng, bnb, bnm, bnv, t2);
    conv1x1_kernel<<<dim3(6, 1, 16), 256>>>(t2, bqw, bqb, bsw, bsb, Qb, Kb);

    float* outL = (float*)d_out;
    float* outR = outL + (size_t)B_ * C_ * HW_;
    attention_kernel<<<dim3(H_, B_, 2), 256, ATT_SMEM>>>(Qb, Kb, xL, xR, dL, dR,
                                                         outL, outR);
}

// round 6
// speedup vs baseline: 1.1079x; 1.1079x over previous
#include <cuda_runtime.h>
#include <cstddef>

// ---------------------------------------------------------------------------
// Problem constants
// ---------------------------------------------------------------------------
constexpr int B_  = 2;
constexpr int C_  = 64;
constexpr int C4_ = 256;
constexpr int H_  = 64;
constexpr int W_  = 96;
constexpr int HW_ = H_ * W_;
constexpr int NSB = 2 * B_;   // side * batch slots

typedef unsigned long long ull;

// Scratch (device globals: no allocations allowed). Layout [side*B+b][C4][HW]
__device__ float g_t1[(size_t)NSB * C4_ * HW_];
__device__ float g_t2[(size_t)NSB * C4_ * HW_];
__device__ float g_Q [(size_t)B_ * C_  * HW_];
__device__ float g_K [(size_t)B_ * C_  * HW_];

// ---------------------------------------------------------------------------
// f32x2 helpers (sm_100+ packed fp32 — exact, two independent IEEE FMAs)
// ---------------------------------------------------------------------------
__device__ __forceinline__ ull pk2(float a, float b) {
    ull r;
    asm("mov.b64 %0, {%1, %2};" : "=l"(r)
        : "r"(__float_as_uint(a)), "r"(__float_as_uint(b)));
    return r;
}
__device__ __forceinline__ void fma2(ull& d, ull a, ull b) {
    asm("fma.rn.f32x2 %0, %1, %2, %0;" : "+l"(d) : "l"(a), "l"(b));
}
__device__ __forceinline__ void unpk2(ull v, float& lo, float& hi) {
    unsigned l, h;
    asm("mov.b64 {%0, %1}, %2;" : "=r"(l), "=r"(h) : "l"(v));
    lo = __uint_as_float(l); hi = __uint_as_float(h);
}

// ---------------------------------------------------------------------------
// Grouped 3x3 conv (groups=4, in=out=256ch), stride 1, pad 1. Both sides in
// one launch: z = s*8 + b*4 + g.  (R4 configuration — known good.)
// MODE 1: input = BN(cat[side]) on load; output = leaky(conv + bias)
// MODE 2: input = t1[side]; output = conv + bias + BN(cat[side]) residual
// Tile 8 rows x 32 cols x 64 oc per block; 256 threads; f32x2 math.
// ---------------------------------------------------------------------------
constexpr int TH   = 8;
constexpr int TW   = 32;
constexpr int ICB  = 8;
constexpr int INROW   = TW + 2;   // 34 valid cols
constexpr int INPITCH = 36;       // even pitch -> float2-aligned rows

constexpr int CONV_W2   = ICB * 9 * 64;            // ull count
constexpr int CONV_IN   = ICB * 10 * INPITCH;      // float count
constexpr int CONV_SMEM = CONV_W2 * 8 + CONV_IN * 4 + 2 * 64 * 4;

template <int MODE>
__global__ __launch_bounds__(256, 2)
void conv3x3_kernel(const float* __restrict__ catL,
                    const float* __restrict__ catR,
                    const float* __restrict__ tin,
                    const float* __restrict__ wgt,   // (256, 64, 3, 3)
                    const float* __restrict__ bias,  // (256)
                    const float* __restrict__ bn_g,
                    const float* __restrict__ bn_b,
                    const float* __restrict__ bn_m,
                    const float* __restrict__ bn_v,
                    float* __restrict__ out)
{
    extern __shared__ unsigned char csm[];
    ull*   s_w2 = (ull*)csm;                       // [oc*72 + c*9 + tap]
    float* s_in = (float*)(s_w2 + CONV_W2);        // [c][10][36]
    float* s_sc = s_in + CONV_IN;
    float* s_sh = s_sc + 64;

    const int tid = threadIdx.x;
    const int bz  = blockIdx.z;        // s*8 + b*4 + g
    const int s   = bz >> 3;
    const int b   = (bz >> 2) & 1;
    const int g   = bz & 3;
    const int sb  = s * B_ + b;
    const int y0  = blockIdx.y * TH;
    const int x0  = blockIdx.x * TW;
    const int chbase = g * 64;

    const float* cat = s ? catR : catL;

    if (tid < 64) {
        const int ch = chbase + tid;
        const float sc = bn_g[ch] * rsqrtf(bn_v[ch] + 1e-5f);
        s_sc[tid] = sc;
        s_sh[tid] = bn_b[ch] - bn_m[ch] * sc;
    }

    const int og   = tid >> 5;        // 0..7 (out-channel octet)
    const int p    = tid & 31;
    const int rowp = p >> 2;          // 0..7
    const int colp = (p & 3) * 8;     // 0,8,16,24

    ull acc2[8][4];
#pragma unroll
    for (int o = 0; o < 8; o++)
#pragma unroll
        for (int q = 0; q < 4; q++) acc2[o][q] = 0ULL;

    const float* inb = (MODE == 1)
        ? cat + (size_t)(b * C4_ + chbase) * HW_
        : tin + (size_t)(sb * C4_ + chbase) * HW_;

    __syncthreads();  // s_sc/s_sh ready

    for (int icb = 0; icb < 64; icb += ICB) {
        // stage input tile (BN on load for MODE 1)
        for (int idx = tid; idx < ICB * 10 * INROW; idx += 256) {
            const int c   = idx / (10 * INROW);
            const int rem = idx % (10 * INROW);
            const int r   = rem / INROW;
            const int cc  = rem % INROW;
            const int gy  = y0 - 1 + r;
            const int gx  = x0 - 1 + cc;
            float v = 0.f;
            if ((unsigned)gy < (unsigned)H_ && (unsigned)gx < (unsigned)W_) {
                v = inb[(size_t)(icb + c) * HW_ + gy * W_ + gx];
                if (MODE == 1) v = v * s_sc[icb + c] + s_sh[icb + c];
            }
            s_in[(c * 10 + r) * INPITCH + cc] = v;
        }
        // stage weights duplicated into f32x2: s_w2[oc*72 + c*9 + tap]
        for (int idx = tid; idx < ICB * 576; idx += 256) {
            const int oc  = idx / 72;
            const int r   = idx % 72;    // c*9 + tap
            const int c   = r / 9;
            const int tap = r % 9;
            const float w = wgt[(size_t)(chbase + oc) * 576 + (icb + c) * 9 + tap];
            s_w2[oc * 72 + r] = pk2(w, w);
        }
        __syncthreads();

#pragma unroll 2
        for (int c = 0; c < ICB; c++) {
            float xv[3][10];
#pragma unroll
            for (int kh = 0; kh < 3; kh++) {
                const float* rp = &s_in[(c * 10 + rowp + kh) * INPITCH + colp];
#pragma unroll
                for (int t5 = 0; t5 < 5; t5++) {
                    const float2 v = ((const float2*)rp)[t5];
                    xv[kh][2 * t5]     = v.x;
                    xv[kh][2 * t5 + 1] = v.y;
                }
            }
            const ull* wbase = &s_w2[(og * 8) * 72 + c * 9];
#pragma unroll
            for (int kh = 0; kh < 3; kh++) {
#pragma unroll
                for (int t = 0; t < 3; t++) {
                    const int tap = kh * 3 + t;
                    const ull xp0 = pk2(xv[kh][t],     xv[kh][t + 1]);
                    const ull xp1 = pk2(xv[kh][t + 2], xv[kh][t + 3]);
                    const ull xp2 = pk2(xv[kh][t + 4], xv[kh][t + 5]);
                    const ull xp3 = pk2(xv[kh][t + 6], xv[kh][t + 7]);
#pragma unroll
                    for (int o = 0; o < 8; o++) {
                        const ull w = wbase[o * 72 + tap];   // broadcast
                        fma2(acc2[o][0], w, xp0);
                        fma2(acc2[o][1], w, xp1);
                        fma2(acc2[o][2], w, xp2);
                        fma2(acc2[o][3], w, xp3);
                    }
                }
            }
        }
        __syncthreads();
    }

    // epilogue
    const float* catb = cat + (size_t)(b * C4_ + chbase) * HW_;
    float*       outb = out + (size_t)(sb * C4_ + chbase) * HW_;
    const int y = y0 + rowp;
#pragma unroll
    for (int o = 0; o < 8; o++) {
        const int oc = og * 8 + o;
        const float bv = bias[chbase + oc];
#pragma unroll
        for (int pq = 0; pq < 4; pq++) {
            float v0, v1;
            unpk2(acc2[o][pq], v0, v1);
#pragma unroll
            for (int half = 0; half < 2; half++) {
                const int x = x0 + colp + 2 * pq + half;
                float v = (half ? v1 : v0) + bv;
                if (MODE == 1) {
                    v = (v > 0.f) ? v : 0.1f * v;         // LeakyReLU(0.1)
                } else {
                    const float cv = catb[(size_t)oc * HW_ + y * W_ + x];
                    v += cv * s_sc[oc] + s_sh[oc];
                }
                outb[(size_t)oc * HW_ + y * W_ + x] = v;
            }
        }
    }
}

// ---------------------------------------------------------------------------
// Grouped 1x1 conv: 64oc <- 256ic, groups=4 (16oc per group reads 64ic).
// z = s*8 + b*4 + g. Each thread: 4 consecutive pixels, all 16 oc.
// ---------------------------------------------------------------------------
__global__ __launch_bounds__(256)
void conv1x1_kernel(const float* __restrict__ in,    // t2 [sb][256][HW]
                    const float* __restrict__ bqw, const float* __restrict__ bqb,
                    const float* __restrict__ bsw, const float* __restrict__ bsb,
                    float* __restrict__ Qb, float* __restrict__ Kb)
{
    __shared__ ull s_wt[16 * 64];   // duplicated weights, 8KB

    const int tid = threadIdx.x;
    const int bz  = blockIdx.z;
    const int s   = bz >> 3;
    const int b   = (bz >> 2) & 1;
    const int g   = bz & 3;

    const float* wsel = s ? bsw : bqw;
    const float* bsel = s ? bsb : bqb;

    for (int idx = tid; idx < 1024; idx += 256) {
        const int o  = idx >> 6;
        const int ic = idx & 63;
        const float w = wsel[(g * 16 + o) * 64 + ic];
        s_wt[idx] = pk2(w, w);
    }
    __syncthreads();

    const int px0 = blockIdx.x * 1024 + tid * 4;
    const float* ip = in + (size_t)((s * B_ + b) * C4_ + g * 64) * HW_ + px0;

    ull acc[16][2];
#pragma unroll
    for (int o = 0; o < 16; o++) {
        const float bv = bsel[g * 16 + o];
        acc[o][0] = pk2(bv, bv);
        acc[o][1] = pk2(bv, bv);
    }

    for (int ic = 0; ic < 64; ic++) {
        const float4 v = *(const float4*)&ip[(size_t)ic * HW_];
        const ull v01 = pk2(v.x, v.y);
        const ull v23 = pk2(v.z, v.w);
        const ull* wp = &s_wt[ic];
#pragma unroll
        for (int o = 0; o < 16; o++) {
            const ull w = wp[o * 64];   // broadcast
            fma2(acc[o][0], w, v01);
            fma2(acc[o][1], w, v23);
        }
    }

    float* op = (s ? Kb : Qb) + (size_t)(b * C_ + g * 16) * HW_ + px0;
#pragma unroll
    for (int o = 0; o < 16; o++) {
        float4 r;
        unpk2(acc[o][0], r.x, r.y);
        unpk2(acc[o][1], r.z, r.w);
        *(float4*)&op[(size_t)o * HW_] = r;
    }
}

// ---------------------------------------------------------------------------
// Attention kernel. Grid (H, B, dir*2 + jhalf) = 512 blocks. 256 threads.
// Each block handles 48 output columns (one half of the row).
// dir 0 = r2l (K-window/Q-center -> outL from xR)
// dir 1 = l2r (Q-window/K-center -> outR from xL, value coords still r2l).
// Window strips channel-paired as float2; 4-col zero padding -> no predicates.
// Mean subtraction dropped (softmax-invariant).
// ---------------------------------------------------------------------------
constexpr int ROWP2  = 105;             // row pitch in float2 units
constexpr int CSTR2  = 8 * ROWP2 + 5;   // 845, channel-pair stride (float2)
constexpr int NPAIR  = 4;               // channel pairs per chunk (8 channels)
constexpr int WIN_F2 = NPAIR * CSTR2;   // 3380 float2
constexpr int CEN_F2 = NPAIR * 48;      // 192 float2
constexpr int MPITCH = 66;
constexpr int M_F    = 48 * MPITCH;     // 3168 floats
constexpr int OUT_F  = 8 * 48;          // 384 floats
constexpr int ATT_SMEM = WIN_F2 * 8 + CEN_F2 * 8 + M_F * 4 + OUT_F * 4 + 5 * 48 * 4;

__global__ __launch_bounds__(256, 4)
void attention_kernel(const float* __restrict__ Qf, const float* __restrict__ Kf,
                      const float* __restrict__ xL, const float* __restrict__ xR,
                      const int* __restrict__ dL, const int* __restrict__ dR,
                      float* __restrict__ outL, float* __restrict__ outR)
{
    extern __shared__ float smem[];
    float2* s_win2 = (float2*)smem;                 // WIN_F2
    float2* s_cen2 = s_win2 + WIN_F2;               // CEN_F2
    float*  s_M    = (float*)(s_cen2 + CEN_F2);     // M_F
    float*  s_out  = s_M + M_F;                     // OUT_F
    int*    s_cc   = (int*)(s_out + OUT_F);         // 48  logits centers
    int*    s_cv   = s_cc + 48;                     // 48  value centers (= cr)
    int*    s_sval = s_cv + 48;                     // 48  softmax validity
    int*    s_vval = s_sval + 48;                   // 48  value validity (= vR)
    float*  s_mask = (float*)(s_vval + 48);         // 48  output mask

    const int i   = blockIdx.x;
    const int b   = blockIdx.y;
    const int z   = blockIdx.z & 1;                 // 0=r2l, 1=l2r
    const int j0  = (blockIdx.z >> 1) * 48;         // column-half origin
    const int tid = threadIdx.x;

    if (tid < 48) {
        const int j  = j0 + tid;
        const int dl = dL[(b * H_ + i) * W_ + j];
        const int dr = dR[(b * H_ + i) * W_ + j];
        const int cr = max(j - dl, 0);
        const int cl = min(j + dr, W_ - 1);
        const int rowok = (i + 4) < H_;
        const int vR = (rowok && cr < W_ - 4) ? 1 : 0;
        const int vL = (rowok && cl < W_ - 4) ? 1 : 0;
        s_cc[tid]   = z ? cl : cr;
        s_cv[tid]   = cr;                           // value coords always r2l
        s_sval[tid] = z ? vL : vR;
        s_vval[tid] = vR;                           // value validity always vR
        s_mask[tid] = z ? ((j + dr <= W_ - 1) ? 1.f : 0.f)
                        : ((j - dl >= 0)      ? 1.f : 0.f);
    }
    for (int idx = tid; idx < WIN_F2; idx += 256)
        s_win2[idx] = make_float2(0.f, 0.f);        // incl. pad columns
    for (int idx = tid; idx < M_F; idx += 256) s_M[idx] = 0.f;
    __syncthreads();

    const float* winsrc = z ? Qf : Kf;
    const float* censrc = z ? Kf : Qf;
    const int jl   = tid >> 2;           // 0..63 (active < 48 in compute)
    const int kq   = tid & 3;
    const int koff = kq * 16;

    // ---- logits: 8 chunks of 4 channel pairs ----
    for (int cb = 0; cb < 8; cb++) {
        const int c0 = cb * 8;
        const float* wsb = winsrc + (size_t)(b * C_ + c0) * HW_;
        for (int idx = tid; idx < NPAIR * 768; idx += 256) {
            const int cp  = idx / 768;
            const int rem = idx - cp * 768;          // a*96 + col
            const int a   = rem / 96;
            const int col = rem - a * 96;
            const int gy  = i - 4 + a;
            float v0 = 0.f, v1 = 0.f;
            if ((unsigned)gy < (unsigned)H_) {
                const size_t o = (size_t)(2 * cp) * HW_ + gy * W_ + col;
                v0 = wsb[o];
                v1 = wsb[o + HW_];
            }
            s_win2[cp * CSTR2 + a * ROWP2 + 4 + col] = make_float2(v0, v1);
        }
        const float* csb = censrc + (size_t)(b * C_ + c0) * HW_ + (size_t)i * W_ + j0;
        for (int idx = tid; idx < NPAIR * 48; idx += 256) {
            const int cp = idx / 48, jj = idx - cp * 48;
            const size_t o = (size_t)(2 * cp) * HW_ + jj;
            s_cen2[idx] = make_float2(csb[o], csb[o + HW_]);
        }
        __syncthreads();

        if (tid < 192) {
            const int cc = s_cc[jl];
            float acc[16];
#pragma unroll
            for (int kk = 0; kk < 16; kk++) acc[kk] = 0.f;
#pragma unroll
            for (int cp = 0; cp < NPAIR; cp++) {
                const float2 cen = s_cen2[cp * 48 + jl];
                const float2* wb = s_win2 + cp * CSTR2 + cc + (kq * 2) * ROWP2;
#pragma unroll
                for (int kk = 0; kk < 16; kk++) {
                    const float2 w = wb[(kk >> 3) * ROWP2 + (kk & 7)];
                    acc[kk] = fmaf(cen.x, w.x, fmaf(cen.y, w.y, acc[kk]));
                }
            }
            float* Mrow = s_M + jl * MPITCH + koff;
#pragma unroll
            for (int kk = 0; kk < 16; kk++) Mrow[kk] += acc[kk];
        }
        __syncthreads();
    }

    // ---- softmax ----
    if (tid < 48) {
        float* row = s_M + tid * MPITCH;
        if (!s_sval[tid]) {
#pragma unroll
            for (int k = 0; k < 64; k++) row[k] = 1.f / 64.f;
        } else {
            float mx = row[0];
#pragma unroll
            for (int k = 1; k < 64; k++) mx = fmaxf(mx, row[k]);
            float ssum = 0.f;
#pragma unroll
            for (int k = 0; k < 64; k++) {
                const float e = __expf(row[k] - mx);
                row[k] = e; ssum += e;
            }
            const float inv = 1.f / ssum;
#pragma unroll
            for (int k = 0; k < 64; k++) row[k] *= inv;
        }
    }
    __syncthreads();

    // ---- value pass: 8 chunks of 4 channel pairs ----
    const float* valsrc  = z ? xL : xR;
    const float* basesrc = z ? xR : xL;
    float*       outdst  = z ? outR : outL;
    const int cpair = tid & 3;
    const int jg    = tid >> 2;          // 0..63, active < 48

    for (int cb = 0; cb < 8; cb++) {
        const int c0 = cb * 8;
        const float* vsb = valsrc + (size_t)(b * C_ + c0) * HW_;
        for (int idx = tid; idx < NPAIR * 768; idx += 256) {
            const int cp  = idx / 768;
            const int rem = idx - cp * 768;
            const int a   = rem / 96;
            const int col = rem - a * 96;
            const int gy  = i - 4 + a;
            float v0 = 0.f, v1 = 0.f;
            if ((unsigned)gy < (unsigned)H_) {
                const size_t o = (size_t)(2 * cp) * HW_ + gy * W_ + col;
                v0 = vsb[o];
                v1 = vsb[o + HW_];
            }
            s_win2[cp * CSTR2 + a * ROWP2 + 4 + col] = make_float2(v0, v1);
        }
        __syncthreads();

        if (jg < 48) {
            float aL = 0.f, aH = 0.f;
            if (s_vval[jg]) {
                const float2* wb   = s_win2 + cpair * CSTR2 + s_cv[jg];
                const float*  Mrow = s_M + jg * MPITCH;
#pragma unroll
                for (int kp = 0; kp < 32; kp++) {
                    const float2 mv = *(const float2*)(Mrow + 2 * kp);
                    const int k0 = 2 * kp, k1 = 2 * kp + 1;
                    const float2 w0 = wb[(k0 >> 3) * ROWP2 + (k0 & 7)];
                    const float2 w1 = wb[(k1 >> 3) * ROWP2 + (k1 & 7)];
                    aL = fmaf(mv.x, w0.x, fmaf(mv.y, w1.x, aL));
                    aH = fmaf(mv.x, w0.y, fmaf(mv.y, w1.y, aH));
                }
            }
            s_out[(2 * cpair) * 48 + jg]     = aL * s_mask[jg];
            s_out[(2 * cpair + 1) * 48 + jg] = aH * s_mask[jg];
        }
        __syncthreads();

        for (int t = 0; t < 2; t++) {
            const int idx = tid + t * 256;
            if (idx < OUT_F) {
                const int c = idx / 48, j = idx - c * 48;
                const size_t gidx = ((size_t)(b * C_ + c0 + c) * H_ + i) * W_ + j0 + j;
                outdst[gidx] = basesrc[gidx] + s_out[idx];
            }
        }
        __syncthreads();
    }
}

// ---------------------------------------------------------------------------
// Host launcher
// ---------------------------------------------------------------------------
extern "C" void kernel_launch(void* const* d_in, const int* in_sizes, int n_in,
                              void* d_out, int out_size)
{
    const float *xL, *xR, *catL, *catR;
    const float *bng, *bnb, *bnm, *bnv, *w1, *b1, *w2, *b2, *bqw, *bqb, *bsw, *bsb;
    const int *dL, *dR;

    const bool dict_order = (n_in >= 18) && (in_sizes[4] == B_ * H_ * W_);
    if (dict_order) {
        xL   = (const float*)d_in[0];  xR   = (const float*)d_in[1];
        catL = (const float*)d_in[2];  catR = (const float*)d_in[3];
        dL   = (const int*)  d_in[4];  dR   = (const int*)  d_in[5];
        bng  = (const float*)d_in[6];  bnb  = (const float*)d_in[7];
        bnm  = (const float*)d_in[8];  bnv  = (const float*)d_in[9];
        w1   = (const float*)d_in[10]; b1   = (const float*)d_in[11];
        w2   = (const float*)d_in[12]; b2   = (const float*)d_in[13];
        bqw  = (const float*)d_in[14]; bqb  = (const float*)d_in[15];
        bsw  = (const float*)d_in[16]; bsb  = (const float*)d_in[17];
    } else {
        xL   = (const float*)d_in[0];  xR   = (const float*)d_in[1];
        catL = (const float*)d_in[2];  catR = (const float*)d_in[3];
        bng  = (const float*)d_in[4];  bnb  = (const float*)d_in[5];
        bnm  = (const float*)d_in[6];  bnv  = (const float*)d_in[7];
        w1   = (const float*)d_in[8];  b1   = (const float*)d_in[9];
        w2   = (const float*)d_in[10]; b2   = (const float*)d_in[11];
        bqw  = (const float*)d_in[12]; bqb  = (const float*)d_in[13];
        bsw  = (const float*)d_in[14]; bsb  = (const float*)d_in[15];
        dL   = (const int*)  d_in[16]; dR   = (const int*)  d_in[17];
    }

    float *t1, *t2, *Qb, *Kb;
    cudaGetSymbolAddress((void**)&t1, g_t1);
    cudaGetSymbolAddress((void**)&t2, g_t2);
    cudaGetSymbolAddress((void**)&Qb, g_Q);
    cudaGetSymbolAddress((void**)&Kb, g_K);

    cudaFuncSetAttribute(conv3x3_kernel<1>,
                         cudaFuncAttributeMaxDynamicSharedMemorySize, CONV_SMEM);
    cudaFuncSetAttribute(conv3x3_kernel<2>,
                         cudaFuncAttributeMaxDynamicSharedMemorySize, CONV_SMEM);
    cudaFuncSetAttribute(attention_kernel,
                         cudaFuncAttributeMaxDynamicSharedMemorySize, ATT_SMEM);

    const dim3 cgrid(W_ / TW, H_ / TH, NSB * 4);   // (3, 8, 16) = 384 blocks

    conv3x3_kernel<1><<<cgrid, 256, CONV_SMEM>>>(catL, catR, nullptr, w1, b1,
                                                 bng, bnb, bnm, bnv, t1);
    conv3x3_kernel<2><<<cgrid, 256, CONV_SMEM>>>(catL, catR, t1, w2, b2,
                                                 bng, bnb, bnm, bnv, t2);
    conv1x1_kernel<<<dim3(6, 1, 16), 256>>>(t2, bqw, bqb, bsw, bsb, Qb, Kb);

    float* outL = (float*)d_out;
    float* outR = outL + (size_t)B_ * C_ * HW_;
    attention_kernel<<<dim3(H_, B_, 4), 256, ATT_SMEM>>>(Qb, Kb, xL, xR, dL, dR,
                                                         outL, outR);
}